// round 4
// baseline (speedup 1.0000x reference)
#include <cuda_runtime.h>

#define BB 16
#define SS 4096
#define VV 1024
#define INV_SQRT_S 0.015625f   // 1/sqrt(4096)
#define NWG 148                // row-stride = total warps per batch in main kernel

// Scratch (no allocations allowed)
__device__ float g_q[BB * VV];
__device__ float g_u[BB * VV];
__device__ float g_c[BB];
__device__ float g_y[BB * VV];
__device__ float g_A[BB];

// ---------------------------------------------------------------------------
// Zero accumulators
// ---------------------------------------------------------------------------
__global__ void zero_kernel() {
    int i = blockIdx.x * blockDim.x + threadIdx.x;
    if (i < BB * VV) { g_y[i] = 0.f; g_u[i] = 0.f; }
    if (i < BB) { g_A[i] = 0.f; g_c[i] = 0.f; }
}

// ---------------------------------------------------------------------------
// q[b][o] = sum_v Wq[o][v] * pool[b][v] + bq[o]
// Also folds in c[b] += q[b][o] * bk[o]  (removes separate c_kernel)
// ---------------------------------------------------------------------------
__global__ void __launch_bounds__(256) qc_kernel(const float* __restrict__ pool,
                                                 const float* __restrict__ Wq,
                                                 const float* __restrict__ bq,
                                                 const float* __restrict__ bk) {
    const int warp = threadIdx.x >> 5, lane = threadIdx.x & 31;
    const int o = blockIdx.x * 8 + warp;
    __shared__ float ps[16 * 256];
    float acc[16];
#pragma unroll
    for (int b = 0; b < 16; b++) acc[b] = 0.f;

    for (int ch = 0; ch < 4; ch++) {
        __syncthreads();
        for (int i = threadIdx.x; i < 4096; i += 256) {
            int b = i >> 8, v = i & 255;
            ps[i] = pool[b * VV + ch * 256 + v];
        }
        __syncthreads();
#pragma unroll
        for (int j = 0; j < 8; j++) {
            float w = Wq[o * VV + ch * 256 + j * 32 + lane];
#pragma unroll
            for (int b = 0; b < 16; b++)
                acc[b] += w * ps[b * 256 + j * 32 + lane];
        }
    }
    float bqo = 0.f, bko = 0.f;
    if (lane == 0) { bqo = bq[o]; bko = bk[o]; }
#pragma unroll
    for (int b = 0; b < 16; b++) {
        float r = acc[b];
#pragma unroll
        for (int off = 16; off; off >>= 1) r += __shfl_xor_sync(0xffffffffu, r, off);
        if (lane == 0) {
            float qv = r + bqo;
            g_q[b * VV + o] = qv;
            atomicAdd(&g_c[b], qv * bko);
        }
    }
}

// ---------------------------------------------------------------------------
// u[b][v] = sum_o q[b][o] * Wk[o][v]
// ---------------------------------------------------------------------------
__global__ void __launch_bounds__(256) u_kernel(const float* __restrict__ Wk) {
    __shared__ float qs[16 * 32];
    const int v = blockIdx.x * 256 + threadIdx.x;
    const int o0 = blockIdx.y * 32;
    for (int i = threadIdx.x; i < 512; i += 256) {
        int b = i >> 5, oo = i & 31;
        qs[i] = g_q[b * VV + o0 + oo];
    }
    __syncthreads();
    float acc[16];
#pragma unroll
    for (int b = 0; b < 16; b++) acc[b] = 0.f;
    for (int oo = 0; oo < 32; oo++) {
        float w = Wk[(o0 + oo) * VV + v];
#pragma unroll
        for (int b = 0; b < 16; b++) acc[b] += qs[b * 32 + oo] * w;
    }
#pragma unroll
    for (int b = 0; b < 16; b++) atomicAdd(&g_u[b * VV + v], acc[b]);
}

// ---------------------------------------------------------------------------
// Fused main pass over bert_output (single 268 MB read):
//   a = (u_b . x + c_b)/sqrt(S);  y_b += a*x;  A_b += a
// 128-thread CTAs, occ 4 -> grid 37x16 = 592 = exactly one wave on 148 SMs.
// Dot = 8 independent partials + tree combine + 5-step shuffle butterfly.
// ---------------------------------------------------------------------------
__global__ void __launch_bounds__(128, 4) main_kernel(const float* __restrict__ X) {
    const int b = blockIdx.y;
    const int warp = threadIdx.x >> 5, lane = threadIdx.x & 31;
    const int wg = blockIdx.x * 4 + warp;   // 0..147, row stride NWG

    float4 u4[8];
    const float4* ub = reinterpret_cast<const float4*>(g_u + b * VV);
#pragma unroll
    for (int j = 0; j < 8; j++) u4[j] = ub[j * 32 + lane];
    const float cb = g_c[b];

    float yacc[32];
#pragma unroll
    for (int i = 0; i < 32; i++) yacc[i] = 0.f;
    float Aacc = 0.f;

    const float4* Xb = reinterpret_cast<const float4*>(X + (size_t)b * SS * VV);

    for (int row = wg; row < SS; row += NWG) {
        const float4* xr = Xb + (size_t)row * (VV / 4);
        float4 x4[8];
#pragma unroll
        for (int j = 0; j < 8; j++) x4[j] = xr[j * 32 + lane];

        // 8 independent dot partials, tree combine (short dependency chains)
        float p[8];
#pragma unroll
        for (int j = 0; j < 8; j++)
            p[j] = fmaf(x4[j].w, u4[j].w,
                   fmaf(x4[j].z, u4[j].z,
                   fmaf(x4[j].y, u4[j].y, x4[j].x * u4[j].x)));
        float d = ((p[0] + p[1]) + (p[2] + p[3])) + ((p[4] + p[5]) + (p[6] + p[7]));

        // warp butterfly reduction (broadcasts sum to all lanes)
#pragma unroll
        for (int off = 16; off; off >>= 1) d += __shfl_xor_sync(0xffffffffu, d, off);

        const float a = (d + cb) * INV_SQRT_S;
        Aacc += a;
#pragma unroll
        for (int j = 0; j < 8; j++) {
            yacc[j * 4 + 0] = fmaf(a, x4[j].x, yacc[j * 4 + 0]);
            yacc[j * 4 + 1] = fmaf(a, x4[j].y, yacc[j * 4 + 1]);
            yacc[j * 4 + 2] = fmaf(a, x4[j].z, yacc[j * 4 + 2]);
            yacc[j * 4 + 3] = fmaf(a, x4[j].w, yacc[j * 4 + 3]);
        }
    }

    __shared__ float ys[VV];
    __shared__ float As;
    for (int i = threadIdx.x; i < VV; i += 128) ys[i] = 0.f;
    if (threadIdx.x == 0) As = 0.f;
    __syncthreads();
#pragma unroll
    for (int j = 0; j < 8; j++) {
        int col = j * 128 + lane * 4;
        atomicAdd(&ys[col + 0], yacc[j * 4 + 0]);
        atomicAdd(&ys[col + 1], yacc[j * 4 + 1]);
        atomicAdd(&ys[col + 2], yacc[j * 4 + 2]);
        atomicAdd(&ys[col + 3], yacc[j * 4 + 3]);
    }
    if (lane == 0) atomicAdd(&As, Aacc);
    __syncthreads();
    for (int i = threadIdx.x; i < VV; i += 128) atomicAdd(&g_y[b * VV + i], ys[i]);
    if (threadIdx.x == 0) atomicAdd(&g_A[b], As);
}

// ---------------------------------------------------------------------------
// out[b][o] = sum_v Wv[o][v] * y[b][v] + A[b]*bv[o]
// ---------------------------------------------------------------------------
__global__ void __launch_bounds__(256) epilogue_kernel(const float* __restrict__ Wv,
                                                       const float* __restrict__ bv,
                                                       float* __restrict__ out) {
    const int warp = threadIdx.x >> 5, lane = threadIdx.x & 31;
    const int o = blockIdx.x * 8 + warp;
    __shared__ float ysm[16 * 256];
    float acc[16];
#pragma unroll
    for (int b = 0; b < 16; b++) acc[b] = 0.f;

    for (int ch = 0; ch < 4; ch++) {
        __syncthreads();
        for (int i = threadIdx.x; i < 4096; i += 256) {
            int b = i >> 8, v = i & 255;
            ysm[i] = g_y[b * VV + ch * 256 + v];
        }
        __syncthreads();
#pragma unroll
        for (int j = 0; j < 8; j++) {
            float w = Wv[o * VV + ch * 256 + j * 32 + lane];
#pragma unroll
            for (int b = 0; b < 16; b++)
                acc[b] += w * ysm[b * 256 + j * 32 + lane];
        }
    }
#pragma unroll
    for (int b = 0; b < 16; b++) {
        float r = acc[b];
#pragma unroll
        for (int off = 16; off; off >>= 1) r += __shfl_xor_sync(0xffffffffu, r, off);
        if (lane == 0) out[b * VV + o] = r + g_A[b] * bv[o];
    }
}

// ---------------------------------------------------------------------------
extern "C" void kernel_launch(void* const* d_in, const int* in_sizes, int n_in,
                              void* d_out, int out_size) {
    const float* pool = (const float*)d_in[0];
    const float* bert = (const float*)d_in[1];
    const float* Wq   = (const float*)d_in[2];
    const float* bq   = (const float*)d_in[3];
    const float* Wk   = (const float*)d_in[4];
    const float* bk   = (const float*)d_in[5];
    const float* Wv   = (const float*)d_in[6];
    const float* bv   = (const float*)d_in[7];
    float* out = (float*)d_out;

    zero_kernel<<<64, 256>>>();
    qc_kernel<<<128, 256>>>(pool, Wq, bq, bk);
    dim3 ug(4, 32);
    u_kernel<<<ug, 256>>>(Wk);
    dim3 mg(37, 16);
    main_kernel<<<mg, 128>>>(bert);
    epilogue_kernel<<<128, 256>>>(Wv, bv, out);
}

// round 5
// speedup vs baseline: 1.0424x; 1.0424x over previous
#include <cuda_runtime.h>

#define BB 16
#define SS 4096
#define VV 1024
#define INV_SQRT_S 0.015625f   // 1/sqrt(4096)
#define NB 592                 // 148 SMs x 4 CTAs: exactly one resident wave
#define NWARPS (NB * 4)        // 2368

// Scratch (no allocations allowed)
__device__ float g_q[BB * VV];
__device__ float g_u[BB * VV];
__device__ float g_c[BB];
__device__ float g_y[BB * VV];
__device__ float g_A[BB];

// Device-wide sense-reversal barrier state (values persist across replays;
// the protocol only compares against the generation read at entry, so any
// starting value is fine and behavior is deterministic).
__device__ unsigned g_barcnt = 0;
__device__ volatile unsigned g_bargen = 0;

__device__ __forceinline__ void gbar() {
    __syncthreads();
    if (threadIdx.x == 0) {
        __threadfence();                       // publish this block's writes
        unsigned gen = g_bargen;
        if (atomicAdd(&g_barcnt, 1u) == NB - 1u) {
            g_barcnt = 0;
            __threadfence();
            g_bargen = gen + 1u;               // release
        } else {
            while (g_bargen == gen) __nanosleep(64);
        }
    }
    __syncthreads();
    __threadfence();                           // acquire side
}

// warp dot helper: r = sum_v a[v]*x[v] over 1024 elems, broadcast to all lanes
__device__ __forceinline__ float warp_dot1024(const float4* __restrict__ A,
                                              const float4* __restrict__ X,
                                              int lane) {
    float p[8];
#pragma unroll
    for (int j = 0; j < 8; j++) {
        float4 a4 = A[j * 32 + lane];
        float4 x4 = X[j * 32 + lane];
        p[j] = fmaf(a4.w, x4.w, fmaf(a4.z, x4.z, fmaf(a4.y, x4.y, a4.x * x4.x)));
    }
    float d = ((p[0] + p[1]) + (p[2] + p[3])) + ((p[4] + p[5]) + (p[6] + p[7]));
#pragma unroll
    for (int off = 16; off; off >>= 1) d += __shfl_xor_sync(0xffffffffu, d, off);
    return d;
}

// ---------------------------------------------------------------------------
// Single persistent kernel: zero -> q&c -> u -> fused main pass -> epilogue
// ---------------------------------------------------------------------------
__global__ void __launch_bounds__(128, 4) fused_kernel(
        const float* __restrict__ pool, const float* __restrict__ X,
        const float* __restrict__ Wq, const float* __restrict__ bq,
        const float* __restrict__ Wk, const float* __restrict__ bk,
        const float* __restrict__ Wv, const float* __restrict__ bv,
        float* __restrict__ out) {
    const int warp = threadIdx.x >> 5, lane = threadIdx.x & 31;
    __shared__ float sh[BB * 64];   // 1024 floats, reused per phase
    __shared__ float shA;

    // ---------- Phase 0: zero accumulators ----------
    {
        int t = blockIdx.x * 128 + threadIdx.x;
        if (t < BB * VV) { g_u[t] = 0.f; g_y[t] = 0.f; }
        if (t < BB) { g_c[t] = 0.f; g_A[t] = 0.f; }
    }
    gbar();

    // ---------- Phase A: q[b][o] = Wq[o].pool[b] + bq[o];  c[b] += q*bk[o] ----------
    {
        const int W = blockIdx.x * 4 + warp;
        int p0 = W * 7;
        int p1 = p0 + 7; if (p1 > BB * VV) p1 = BB * VV;
        for (int p = p0; p < p1; p++) {
            const int b = p >> 10, o = p & 1023;
            float r = warp_dot1024((const float4*)(Wq + (size_t)o * VV),
                                   (const float4*)(pool + (size_t)b * VV), lane);
            if (lane == 0) {
                float qv = r + bq[o];
                g_q[p] = qv;
                atomicAdd(&g_c[b], qv * bk[o]);
            }
        }
    }
    gbar();

    // ---------- Phase B: u[b][v] = sum_o q[b][o]*Wk[o][v] ----------
    // 64 worker blocks: (och in 0..3, vch in 0..3, bg in 0..3); 4 batches/block.
    if (blockIdx.x < 64) {
        const int id = blockIdx.x;
        const int och = id >> 4, vch = (id >> 2) & 3, bg = id & 3;
        for (int i = threadIdx.x; i < 1024; i += 128) {
            int b4 = i >> 8, oo = i & 255;
            sh[i] = g_q[(size_t)(bg * 4 + b4) * VV + och * 256 + oo];
        }
        __syncthreads();
        const int v = vch * 256 + threadIdx.x * 2;
        const float2* wk = (const float2*)(Wk + (size_t)(och * 256) * VV + v);
        float2 a0 = {0.f, 0.f}, a1 = {0.f, 0.f}, a2 = {0.f, 0.f}, a3 = {0.f, 0.f};
        for (int oo = 0; oo < 256; oo += 4) {
#pragma unroll
            for (int t = 0; t < 4; t++) {
                float2 w = wk[(size_t)(oo + t) * (VV / 2)];
                float q0 = sh[0 * 256 + oo + t], q1 = sh[1 * 256 + oo + t];
                float q2 = sh[2 * 256 + oo + t], q3 = sh[3 * 256 + oo + t];
                a0.x = fmaf(q0, w.x, a0.x); a0.y = fmaf(q0, w.y, a0.y);
                a1.x = fmaf(q1, w.x, a1.x); a1.y = fmaf(q1, w.y, a1.y);
                a2.x = fmaf(q2, w.x, a2.x); a2.y = fmaf(q2, w.y, a2.y);
                a3.x = fmaf(q3, w.x, a3.x); a3.y = fmaf(q3, w.y, a3.y);
            }
        }
        float* u0 = g_u + (size_t)(bg * 4 + 0) * VV + v;
        float* u1 = g_u + (size_t)(bg * 4 + 1) * VV + v;
        float* u2 = g_u + (size_t)(bg * 4 + 2) * VV + v;
        float* u3 = g_u + (size_t)(bg * 4 + 3) * VV + v;
        atomicAdd(u0, a0.x); atomicAdd(u0 + 1, a0.y);
        atomicAdd(u1, a1.x); atomicAdd(u1 + 1, a1.y);
        atomicAdd(u2, a2.x); atomicAdd(u2 + 1, a2.y);
        atomicAdd(u3, a3.x); atomicAdd(u3 + 1, a3.y);
    }
    gbar();

    // ---------- Phase C: fused main pass over bert_output ----------
    {
        const int b = blockIdx.x & 15;
        const int grp = blockIdx.x >> 4;          // 0..36
        const int wg = grp * 4 + warp;            // 0..147

        float4 u4[8];
        const float4* ub = (const float4*)(g_u + (size_t)b * VV);
#pragma unroll
        for (int j = 0; j < 8; j++) u4[j] = ub[j * 32 + lane];
        const float cb = g_c[b];

        float yacc[32];
#pragma unroll
        for (int i = 0; i < 32; i++) yacc[i] = 0.f;
        float Aacc = 0.f;

        const float4* Xb = (const float4*)(X + (size_t)b * SS * VV);
        for (int row = wg; row < SS; row += 148) {
            const float4* xr = Xb + (size_t)row * (VV / 4);
            float4 x4[8];
#pragma unroll
            for (int j = 0; j < 8; j++) x4[j] = xr[j * 32 + lane];

            float p[8];
#pragma unroll
            for (int j = 0; j < 8; j++)
                p[j] = fmaf(x4[j].w, u4[j].w,
                       fmaf(x4[j].z, u4[j].z,
                       fmaf(x4[j].y, u4[j].y, x4[j].x * u4[j].x)));
            float d = ((p[0] + p[1]) + (p[2] + p[3])) + ((p[4] + p[5]) + (p[6] + p[7]));
#pragma unroll
            for (int off = 16; off; off >>= 1) d += __shfl_xor_sync(0xffffffffu, d, off);

            const float a = (d + cb) * INV_SQRT_S;
            Aacc += a;
#pragma unroll
            for (int j = 0; j < 8; j++) {
                yacc[j * 4 + 0] = fmaf(a, x4[j].x, yacc[j * 4 + 0]);
                yacc[j * 4 + 1] = fmaf(a, x4[j].y, yacc[j * 4 + 1]);
                yacc[j * 4 + 2] = fmaf(a, x4[j].z, yacc[j * 4 + 2]);
                yacc[j * 4 + 3] = fmaf(a, x4[j].w, yacc[j * 4 + 3]);
            }
        }

        for (int i = threadIdx.x; i < VV; i += 128) sh[i] = 0.f;
        if (threadIdx.x == 0) shA = 0.f;
        __syncthreads();
#pragma unroll
        for (int j = 0; j < 8; j++) {
            int col = j * 128 + lane * 4;
            atomicAdd(&sh[col + 0], yacc[j * 4 + 0]);
            atomicAdd(&sh[col + 1], yacc[j * 4 + 1]);
            atomicAdd(&sh[col + 2], yacc[j * 4 + 2]);
            atomicAdd(&sh[col + 3], yacc[j * 4 + 3]);
        }
        if (lane == 0) atomicAdd(&shA, Aacc);
        __syncthreads();
        for (int i = threadIdx.x; i < VV; i += 128) atomicAdd(&g_y[(size_t)b * VV + i], sh[i]);
        if (threadIdx.x == 0) atomicAdd(&g_A[b], shA);
    }
    gbar();

    // ---------- Phase D: out[b][o] = Wv[o].y[b] + A[b]*bv[o] ----------
    {
        const int W = blockIdx.x * 4 + warp;
        int p0 = W * 7;
        int p1 = p0 + 7; if (p1 > BB * VV) p1 = BB * VV;
        for (int p = p0; p < p1; p++) {
            const int b = p >> 10, o = p & 1023;
            float r = warp_dot1024((const float4*)(Wv + (size_t)o * VV),
                                   (const float4*)(g_y + (size_t)b * VV), lane);
            if (lane == 0) out[p] = r + g_A[b] * bv[o];
        }
    }
}

// ---------------------------------------------------------------------------
extern "C" void kernel_launch(void* const* d_in, const int* in_sizes, int n_in,
                              void* d_out, int out_size) {
    const float* pool = (const float*)d_in[0];
    const float* bert = (const float*)d_in[1];
    const float* Wq   = (const float*)d_in[2];
    const float* bq   = (const float*)d_in[3];
    const float* Wk   = (const float*)d_in[4];
    const float* bk   = (const float*)d_in[5];
    const float* Wv   = (const float*)d_in[6];
    const float* bv   = (const float*)d_in[7];
    float* out = (float*)d_out;

    fused_kernel<<<NB, 128>>>(pool, bert, Wq, bq, Wk, bk, Wv, bv, out);
}

// round 6
// speedup vs baseline: 1.2106x; 1.1614x over previous
#include <cuda_runtime.h>

#define BB 16
#define SS 4096
#define VV 1024
#define INV_SQRT_S 0.015625f   // 1/sqrt(4096)
#define NB 592                 // 148 SMs x 4 CTAs: exactly one resident wave

// Scratch (no allocations allowed)
__device__ float g_q[BB * VV];
__device__ float g_u[BB * VV];
__device__ float g_c[BB];
__device__ float g_y[BB * VV];
__device__ float g_A[BB];

// Device-wide sense-reversal barrier (generation-based: safe across graph replays)
__device__ unsigned g_barcnt = 0;
__device__ volatile unsigned g_bargen = 0;

__device__ __forceinline__ void gbar() {
    __syncthreads();
    if (threadIdx.x == 0) {
        __threadfence();
        unsigned gen = g_bargen;
        if (atomicAdd(&g_barcnt, 1u) == NB - 1u) {
            g_barcnt = 0;
            __threadfence();
            g_bargen = gen + 1u;
        } else {
            while (g_bargen == gen) __nanosleep(64);
        }
    }
    __syncthreads();
    __threadfence();
}

// ---------------------------------------------------------------------------
// Single persistent kernel:
//   A: q (warp per o, Wq read ONCE) + zeroing by idle blocks
//   B: u = q @ Wk (64 blocks) + c[b] = q.bk (16 blocks, exact, no atomics)
//   C: fused main pass over bert_output (268 MB single read)
//   D: out = Wv @ y + A*bv (warp per o, Wv read ONCE)
// ---------------------------------------------------------------------------
__global__ void __launch_bounds__(128, 4) fused_kernel(
        const float* __restrict__ pool, const float* __restrict__ X,
        const float* __restrict__ Wq, const float* __restrict__ bq,
        const float* __restrict__ Wk, const float* __restrict__ bk,
        const float* __restrict__ Wv, const float* __restrict__ bv,
        float* __restrict__ out) {
    const int warp = threadIdx.x >> 5, lane = threadIdx.x & 31;
    __shared__ float sh[BB * 64];   // 1024 floats, reused per phase
    __shared__ float shA;

    // ---------- Phase A: q[b][o] = Wq[o].pool[b] + bq[o] ----------
    if (blockIdx.x < 256) {
        const int o = blockIdx.x * 4 + warp;
        const float4* wrow = (const float4*)(Wq + (size_t)o * VV);
        float4 w4[8];
#pragma unroll
        for (int j = 0; j < 8; j++) w4[j] = wrow[j * 32 + lane];

        float acc[16];
#pragma unroll
        for (int b = 0; b < 16; b++) {
            const float4* pr = (const float4*)(pool + (size_t)b * VV);
            float p0 = 0.f, p1 = 0.f;
#pragma unroll
            for (int j = 0; j < 8; j++) {
                float4 x = pr[j * 32 + lane];
                p0 = fmaf(x.x, w4[j].x, fmaf(x.y, w4[j].y, p0));
                p1 = fmaf(x.z, w4[j].z, fmaf(x.w, w4[j].w, p1));
            }
            acc[b] = p0 + p1;
        }
#pragma unroll
        for (int b = 0; b < 16; b++) {
#pragma unroll
            for (int off = 16; off; off >>= 1)
                acc[b] += __shfl_xor_sync(0xffffffffu, acc[b], off);
        }
        if (lane == 0) {
            float bqo = bq[o];
#pragma unroll
            for (int b = 0; b < 16; b++) g_q[(size_t)b * VV + o] = acc[b] + bqo;
        }
    } else {
        // idle blocks zero the accumulators (replaces Phase 0 + one barrier)
        int t = (blockIdx.x - 256) * 128 + threadIdx.x;
        if (t < BB * VV) { g_u[t] = 0.f; g_y[t] = 0.f; }
        if (t < BB) g_A[t] = 0.f;
    }
    gbar();

    // ---------- Phase B: u[b][v] = sum_o q[b][o]*Wk[o][v];  c[b] = q[b].bk ----------
    if (blockIdx.x < 64) {
        const int id = blockIdx.x;
        const int och = id >> 4, vch = (id >> 2) & 3, bg = id & 3;
        for (int i = threadIdx.x; i < 1024; i += 128) {
            int b4 = i >> 8, oo = i & 255;
            sh[i] = g_q[(size_t)(bg * 4 + b4) * VV + och * 256 + oo];
        }
        __syncthreads();
        const int v = vch * 256 + threadIdx.x * 2;
        const float2* wk = (const float2*)(Wk + (size_t)(och * 256) * VV + v);
        float2 a0 = {0.f, 0.f}, a1 = {0.f, 0.f}, a2 = {0.f, 0.f}, a3 = {0.f, 0.f};
        for (int oo = 0; oo < 256; oo += 4) {
#pragma unroll
            for (int t = 0; t < 4; t++) {
                float2 w = wk[(size_t)(oo + t) * (VV / 2)];
                float q0 = sh[0 * 256 + oo + t], q1 = sh[1 * 256 + oo + t];
                float q2 = sh[2 * 256 + oo + t], q3 = sh[3 * 256 + oo + t];
                a0.x = fmaf(q0, w.x, a0.x); a0.y = fmaf(q0, w.y, a0.y);
                a1.x = fmaf(q1, w.x, a1.x); a1.y = fmaf(q1, w.y, a1.y);
                a2.x = fmaf(q2, w.x, a2.x); a2.y = fmaf(q2, w.y, a2.y);
                a3.x = fmaf(q3, w.x, a3.x); a3.y = fmaf(q3, w.y, a3.y);
            }
        }
        float* u0 = g_u + (size_t)(bg * 4 + 0) * VV + v;
        float* u1 = g_u + (size_t)(bg * 4 + 1) * VV + v;
        float* u2 = g_u + (size_t)(bg * 4 + 2) * VV + v;
        float* u3 = g_u + (size_t)(bg * 4 + 3) * VV + v;
        atomicAdd(u0, a0.x); atomicAdd(u0 + 1, a0.y);
        atomicAdd(u1, a1.x); atomicAdd(u1 + 1, a1.y);
        atomicAdd(u2, a2.x); atomicAdd(u2 + 1, a2.y);
        atomicAdd(u3, a3.x); atomicAdd(u3 + 1, a3.y);
    } else if (blockIdx.x < 80) {
        // c[b] = dot(q[b], bk): one block per b, exact write (no atomics)
        const int b = blockIdx.x - 64;
        float s = 0.f;
#pragma unroll
        for (int j = 0; j < 8; j++) {
            int o = j * 128 + threadIdx.x;
            s = fmaf(g_q[(size_t)b * VV + o], bk[o], s);
        }
#pragma unroll
        for (int off = 16; off; off >>= 1) s += __shfl_xor_sync(0xffffffffu, s, off);
        if (lane == 0) sh[warp] = s;
        __syncthreads();
        if (threadIdx.x == 0) g_c[b] = sh[0] + sh[1] + sh[2] + sh[3];
    }
    gbar();

    // ---------- Phase C: fused main pass over bert_output ----------
    {
        const int b = blockIdx.x & 15;
        const int grp = blockIdx.x >> 4;          // 0..36
        const int wg = grp * 4 + warp;            // 0..147

        float4 u4[8];
        const float4* ub = (const float4*)(g_u + (size_t)b * VV);
#pragma unroll
        for (int j = 0; j < 8; j++) u4[j] = ub[j * 32 + lane];
        const float cb = g_c[b];

        float yacc[32];
#pragma unroll
        for (int i = 0; i < 32; i++) yacc[i] = 0.f;
        float Aacc = 0.f;

        const float4* Xb = (const float4*)(X + (size_t)b * SS * VV);
        for (int row = wg; row < SS; row += 148) {
            const float4* xr = Xb + (size_t)row * (VV / 4);
            float4 x4[8];
#pragma unroll
            for (int j = 0; j < 8; j++) x4[j] = xr[j * 32 + lane];

            float p[8];
#pragma unroll
            for (int j = 0; j < 8; j++)
                p[j] = fmaf(x4[j].w, u4[j].w,
                       fmaf(x4[j].z, u4[j].z,
                       fmaf(x4[j].y, u4[j].y, x4[j].x * u4[j].x)));
            float d = ((p[0] + p[1]) + (p[2] + p[3])) + ((p[4] + p[5]) + (p[6] + p[7]));
#pragma unroll
            for (int off = 16; off; off >>= 1) d += __shfl_xor_sync(0xffffffffu, d, off);

            const float a = (d + cb) * INV_SQRT_S;
            Aacc += a;
#pragma unroll
            for (int j = 0; j < 8; j++) {
                yacc[j * 4 + 0] = fmaf(a, x4[j].x, yacc[j * 4 + 0]);
                yacc[j * 4 + 1] = fmaf(a, x4[j].y, yacc[j * 4 + 1]);
                yacc[j * 4 + 2] = fmaf(a, x4[j].z, yacc[j * 4 + 2]);
                yacc[j * 4 + 3] = fmaf(a, x4[j].w, yacc[j * 4 + 3]);
            }
        }

        __syncthreads();   // sh reuse guard (Phase B readers done at gbar)
        for (int i = threadIdx.x; i < VV; i += 128) sh[i] = 0.f;
        if (threadIdx.x == 0) shA = 0.f;
        __syncthreads();
#pragma unroll
        for (int j = 0; j < 8; j++) {
            int col = j * 128 + lane * 4;
            atomicAdd(&sh[col + 0], yacc[j * 4 + 0]);
            atomicAdd(&sh[col + 1], yacc[j * 4 + 1]);
            atomicAdd(&sh[col + 2], yacc[j * 4 + 2]);
            atomicAdd(&sh[col + 3], yacc[j * 4 + 3]);
        }
        if (lane == 0) atomicAdd(&shA, Aacc);
        __syncthreads();
        for (int i = threadIdx.x; i < VV; i += 128)
            atomicAdd(&g_y[(size_t)b * VV + i], sh[i]);
        if (threadIdx.x == 0) atomicAdd(&g_A[b], shA);
    }
    gbar();

    // ---------- Phase D: out[b][o] = Wv[o].y[b] + A[b]*bv[o] ----------
    if (blockIdx.x < 256) {
        const int o = blockIdx.x * 4 + warp;
        const float4* wrow = (const float4*)(Wv + (size_t)o * VV);
        float4 w4[8];
#pragma unroll
        for (int j = 0; j < 8; j++) w4[j] = wrow[j * 32 + lane];

        float acc[16];
#pragma unroll
        for (int b = 0; b < 16; b++) {
            const float4* yr = (const float4*)(g_y + (size_t)b * VV);
            float p0 = 0.f, p1 = 0.f;
#pragma unroll
            for (int j = 0; j < 8; j++) {
                float4 x = yr[j * 32 + lane];
                p0 = fmaf(x.x, w4[j].x, fmaf(x.y, w4[j].y, p0));
                p1 = fmaf(x.z, w4[j].z, fmaf(x.w, w4[j].w, p1));
            }
            acc[b] = p0 + p1;
        }
#pragma unroll
        for (int b = 0; b < 16; b++) {
#pragma unroll
            for (int off = 16; off; off >>= 1)
                acc[b] += __shfl_xor_sync(0xffffffffu, acc[b], off);
        }
        if (lane == 0) {
            float bvo = bv[o];
#pragma unroll
            for (int b = 0; b < 16; b++)
                out[(size_t)b * VV + o] = acc[b] + g_A[b] * bvo;
        }
    }
}

// ---------------------------------------------------------------------------
extern "C" void kernel_launch(void* const* d_in, const int* in_sizes, int n_in,
                              void* d_out, int out_size) {
    const float* pool = (const float*)d_in[0];
    const float* bert = (const float*)d_in[1];
    const float* Wq   = (const float*)d_in[2];
    const float* bq   = (const float*)d_in[3];
    const float* Wk   = (const float*)d_in[4];
    const float* bk   = (const float*)d_in[5];
    const float* Wv   = (const float*)d_in[6];
    const float* bv   = (const float*)d_in[7];
    float* out = (float*)d_out;

    fused_kernel<<<NB, 128>>>(pool, bert, Wq, bq, Wk, bk, Wv, bv, out);
}

// round 8
// speedup vs baseline: 1.3372x; 1.1046x over previous
#include <cuda_runtime.h>

#define BB 16
#define SS 4096
#define VV 1024
#define INV_SQRT_S 0.015625f   // 1/sqrt(4096)
#define NB 592                 // 148 SMs x 4 CTAs: exactly one resident wave

// Scratch (no allocations allowed)
__device__ float g_q[BB * VV];
__device__ float g_u[BB * VV];
__device__ float g_c[BB];
__device__ float g_y[BB * VV];
__device__ float g_A[BB];

// Device-wide sense-reversal barrier (generation-based: safe across graph replays)
__device__ unsigned g_barcnt = 0;
__device__ volatile unsigned g_bargen = 0;

__device__ __forceinline__ void gbar() {
    __syncthreads();
    if (threadIdx.x == 0) {
        __threadfence();
        unsigned gen = g_bargen;
        if (atomicAdd(&g_barcnt, 1u) == NB - 1u) {
            g_barcnt = 0;
            __threadfence();
            g_bargen = gen + 1u;
        } else {
            while (g_bargen == gen) __nanosleep(64);
        }
    }
    __syncthreads();
    __threadfence();
}

// ---------------------------------------------------------------------------
// Single persistent kernel:
//   A: q = Wq@pool + bq   (256 blocks, pool chunks staged in smem; Wq read once)
//      + zeroing of g_u/g_y/g_A by the other 336 blocks
//   B: u = q @ Wk         (512 blocks, q-chunk in smem, 16 batches in regs,
//                          Wk read exactly once) ; c[b]=q[b].bk (16 blocks)
//   C: fused main pass over bert_output (268 MB single read)
//   D: out = Wv @ y + A*bv (256 blocks, y chunks staged in smem; Wv read once)
// ---------------------------------------------------------------------------
__global__ void __launch_bounds__(128, 4) fused_kernel(
        const float* __restrict__ pool, const float* __restrict__ X,
        const float* __restrict__ Wq, const float* __restrict__ bq,
        const float* __restrict__ Wk, const float* __restrict__ bk,
        const float* __restrict__ Wv, const float* __restrict__ bv,
        float* __restrict__ out) {
    const int warp = threadIdx.x >> 5, lane = threadIdx.x & 31;
    __shared__ float sh[BB * 256];   // 16 KB staging buffer, reused per phase
    __shared__ float shA;

    // ---------- Phase A: q[b][o] = Wq[o].pool[b] + bq[o] ----------
    if (blockIdx.x < 256) {
        const int o = blockIdx.x * 4 + warp;
        float acc[16];
#pragma unroll
        for (int b = 0; b < 16; b++) acc[b] = 0.f;

        for (int ch = 0; ch < 4; ch++) {
            __syncthreads();
            for (int i = threadIdx.x; i < 4096; i += 128) {
                int b = i >> 8, v = i & 255;
                sh[i] = pool[(size_t)b * VV + ch * 256 + v];
            }
            __syncthreads();
#pragma unroll
            for (int j = 0; j < 8; j++) {
                float w = Wq[(size_t)o * VV + ch * 256 + j * 32 + lane];
#pragma unroll
                for (int b = 0; b < 16; b++)
                    acc[b] = fmaf(w, sh[b * 256 + j * 32 + lane], acc[b]);
            }
        }
#pragma unroll
        for (int b = 0; b < 16; b++) {
#pragma unroll
            for (int off = 16; off; off >>= 1)
                acc[b] += __shfl_xor_sync(0xffffffffu, acc[b], off);
        }
        if (lane == 0) {
            float bqo = bq[o];
#pragma unroll
            for (int b = 0; b < 16; b++) g_q[(size_t)b * VV + o] = acc[b] + bqo;
        }
    } else {
        // idle blocks zero the accumulators
        int t = (blockIdx.x - 256) * 128 + threadIdx.x;
        if (t < BB * VV) { g_u[t] = 0.f; g_y[t] = 0.f; }
        if (t < BB) g_A[t] = 0.f;
    }
    gbar();

    // ---------- Phase B: u[b][v] = sum_o q[b][o]*Wk[o][v];  c[b] = q[b].bk ----------
    if (blockIdx.x < 512) {
        const int och = blockIdx.x >> 3;            // 0..63 -> 16 o-rows each
        const int o0 = och * 16;
        const int v = (blockIdx.x & 7) * 128 + threadIdx.x;

        // q chunk [16 b][16 o] = 256 entries, staged by 128 threads (2 each)
        for (int i = threadIdx.x; i < 256; i += 128) {
            int b = i >> 4, oo = i & 15;
            sh[i] = g_q[(size_t)b * VV + o0 + oo];
        }
        __syncthreads();

        float acc[16];
#pragma unroll
        for (int b = 0; b < 16; b++) acc[b] = 0.f;
#pragma unroll
        for (int oo = 0; oo < 16; oo++) {
            float w = Wk[(size_t)(o0 + oo) * VV + v];
#pragma unroll
            for (int b = 0; b < 16; b++)
                acc[b] = fmaf(sh[b * 16 + oo], w, acc[b]);
        }
#pragma unroll
        for (int b = 0; b < 16; b++)
            atomicAdd(&g_u[(size_t)b * VV + v], acc[b]);
    } else if (blockIdx.x < 528) {
        // c[b] = dot(q[b], bk): one block per b, exact write (no atomics)
        const int b = blockIdx.x - 512;
        float s = 0.f;
#pragma unroll
        for (int j = 0; j < 8; j++) {
            int o = j * 128 + threadIdx.x;
            s = fmaf(g_q[(size_t)b * VV + o], bk[o], s);
        }
#pragma unroll
        for (int off = 16; off; off >>= 1) s += __shfl_xor_sync(0xffffffffu, s, off);
        if (lane == 0) sh[warp] = s;
        __syncthreads();
        if (threadIdx.x == 0) g_c[b] = sh[0] + sh[1] + sh[2] + sh[3];
    }
    gbar();

    // ---------- Phase C: fused main pass over bert_output ----------
    {
        const int b = blockIdx.x & 15;
        const int grp = blockIdx.x >> 4;          // 0..36
        const int wg = grp * 4 + warp;            // 0..147

        float4 u4[8];
        const float4* ub = (const float4*)(g_u + (size_t)b * VV);
#pragma unroll
        for (int j = 0; j < 8; j++) u4[j] = ub[j * 32 + lane];
        const float cb = g_c[b];

        float yacc[32];
#pragma unroll
        for (int i = 0; i < 32; i++) yacc[i] = 0.f;
        float Aacc = 0.f;

        const float4* Xb = (const float4*)(X + (size_t)b * SS * VV);
        for (int row = wg; row < SS; row += 148) {
            const float4* xr = Xb + (size_t)row * (VV / 4);
            float4 x4[8];
#pragma unroll
            for (int j = 0; j < 8; j++) x4[j] = xr[j * 32 + lane];

            float p[8];
#pragma unroll
            for (int j = 0; j < 8; j++)
                p[j] = fmaf(x4[j].w, u4[j].w,
                       fmaf(x4[j].z, u4[j].z,
                       fmaf(x4[j].y, u4[j].y, x4[j].x * u4[j].x)));
            float d = ((p[0] + p[1]) + (p[2] + p[3])) + ((p[4] + p[5]) + (p[6] + p[7]));
#pragma unroll
            for (int off = 16; off; off >>= 1) d += __shfl_xor_sync(0xffffffffu, d, off);

            const float a = (d + cb) * INV_SQRT_S;
            Aacc += a;
#pragma unroll
            for (int j = 0; j < 8; j++) {
                yacc[j * 4 + 0] = fmaf(a, x4[j].x, yacc[j * 4 + 0]);
                yacc[j * 4 + 1] = fmaf(a, x4[j].y, yacc[j * 4 + 1]);
                yacc[j * 4 + 2] = fmaf(a, x4[j].z, yacc[j * 4 + 2]);
                yacc[j * 4 + 3] = fmaf(a, x4[j].w, yacc[j * 4 + 3]);
            }
        }

        for (int i = threadIdx.x; i < VV; i += 128) sh[i] = 0.f;
        if (threadIdx.x == 0) shA = 0.f;
        __syncthreads();
#pragma unroll
        for (int j = 0; j < 8; j++) {
            int col = j * 128 + lane * 4;
            atomicAdd(&sh[col + 0], yacc[j * 4 + 0]);
            atomicAdd(&sh[col + 1], yacc[j * 4 + 1]);
            atomicAdd(&sh[col + 2], yacc[j * 4 + 2]);
            atomicAdd(&sh[col + 3], yacc[j * 4 + 3]);
        }
        if (lane == 0) atomicAdd(&shA, Aacc);
        __syncthreads();
        for (int i = threadIdx.x; i < VV; i += 128)
            atomicAdd(&g_y[(size_t)b * VV + i], sh[i]);
        if (threadIdx.x == 0) atomicAdd(&g_A[b], shA);
    }
    gbar();

    // ---------- Phase D: out[b][o] = Wv[o].y[b] + A[b]*bv[o] ----------
    if (blockIdx.x < 256) {
        const int o = blockIdx.x * 4 + warp;
        float acc[16];
#pragma unroll
        for (int b = 0; b < 16; b++) acc[b] = 0.f;

        for (int ch = 0; ch < 4; ch++) {
            __syncthreads();
            for (int i = threadIdx.x; i < 4096; i += 128) {
                int b = i >> 8, v = i & 255;
                sh[i] = g_y[(size_t)b * VV + ch * 256 + v];
            }
            __syncthreads();
#pragma unroll
            for (int j = 0; j < 8; j++) {
                float w = Wv[(size_t)o * VV + ch * 256 + j * 32 + lane];
#pragma unroll
                for (int b = 0; b < 16; b++)
                    acc[b] = fmaf(w, sh[b * 256 + j * 32 + lane], acc[b]);
            }
        }
#pragma unroll
        for (int b = 0; b < 16; b++) {
#pragma unroll
            for (int off = 16; off; off >>= 1)
                acc[b] += __shfl_xor_sync(0xffffffffu, acc[b], off);
        }
        if (lane == 0) {
            float bvo = bv[o];
#pragma unroll
            for (int b = 0; b < 16; b++)
                out[(size_t)b * VV + o] = acc[b] + g_A[b] * bvo;
        }
    }
}

// ---------------------------------------------------------------------------
extern "C" void kernel_launch(void* const* d_in, const int* in_sizes, int n_in,
                              void* d_out, int out_size) {
    const float* pool = (const float*)d_in[0];
    const float* bert = (const float*)d_in[1];
    const float* Wq   = (const float*)d_in[2];
    const float* bq   = (const float*)d_in[3];
    const float* Wk   = (const float*)d_in[4];
    const float* bk   = (const float*)d_in[5];
    const float* Wv   = (const float*)d_in[6];
    const float* bv   = (const float*)d_in[7];
    float* out = (float*)d_out;

    fused_kernel<<<NB, 128>>>(pool, bert, Wq, bq, Wk, bk, Wv, bv, out);
}